// round 4
// baseline (speedup 1.0000x reference)
#include <cuda_runtime.h>

#define B_ 8
#define N_ 1024
#define H_ 8
#define D_ 32

// QKV scratch: [s][b][h][n][d], s in {Q,K,V}
__device__ float g_qkv[3u * B_ * H_ * N_ * D_];  // 25.2 MB

// ---------------------------------------------------------------------------
// Kernel 1: QKV projection (at fp32 FMA floor; unchanged)
// ---------------------------------------------------------------------------
__global__ __launch_bounds__(256) void qkv_gemm(
    const float* __restrict__ x, const float* __restrict__ W,
    const float* __restrict__ bias)
{
    __shared__ float As[64][33];
    __shared__ float Bs[32][64];

    const int tid = threadIdx.x;
    const int ty = tid >> 4, tx = tid & 15;
    const int rb = blockIdx.y * 64;
    const int cb = blockIdx.x * 64;

    float c[4][4] = {};

    for (int k0 = 0; k0 < 256; k0 += 32) {
        #pragma unroll
        for (int i = tid; i < 64 * 32; i += 256) {
            int r = i >> 5, k = i & 31;
            As[r][k] = x[(rb + r) * 256 + k0 + k];
        }
        #pragma unroll
        for (int i = tid; i < 32 * 64; i += 256) {
            int k = i >> 6, cc = i & 63;
            Bs[k][cc] = W[(k0 + k) * 768 + cb + cc];
        }
        __syncthreads();

        #pragma unroll
        for (int kk = 0; kk < 32; kk++) {
            float a0 = As[ty * 4 + 0][kk];
            float a1 = As[ty * 4 + 1][kk];
            float a2 = As[ty * 4 + 2][kk];
            float a3 = As[ty * 4 + 3][kk];
            float4 bv = *(const float4*)&Bs[kk][tx * 4];
            c[0][0] += a0 * bv.x; c[0][1] += a0 * bv.y; c[0][2] += a0 * bv.z; c[0][3] += a0 * bv.w;
            c[1][0] += a1 * bv.x; c[1][1] += a1 * bv.y; c[1][2] += a1 * bv.z; c[1][3] += a1 * bv.w;
            c[2][0] += a2 * bv.x; c[2][1] += a2 * bv.y; c[2][2] += a2 * bv.z; c[2][3] += a2 * bv.w;
            c[3][0] += a3 * bv.x; c[3][1] += a3 * bv.y; c[3][2] += a3 * bv.z; c[3][3] += a3 * bv.w;
        }
        __syncthreads();
    }

    const int c0  = cb + tx * 4;
    const int s   = c0 >> 8;
    const int rem = c0 & 255;
    const int h   = rem >> 5;
    const int d   = rem & 31;
    float4 bb = *(const float4*)&bias[c0];
    #pragma unroll
    for (int j = 0; j < 4; j++) {
        int r = rb + ty * 4 + j;
        int b = r >> 10, n = r & 1023;
        float4 v = make_float4(c[j][0] + bb.x, c[j][1] + bb.y,
                               c[j][2] + bb.z, c[j][3] + bb.w);
        *(float4*)&g_qkv[((((s * 8 + b) * 8 + h) * 1024 + n) << 5) + d] = v;
    }
}

// ---------------------------------------------------------------------------
// Kernel 2: fused moire attention, static-max softmax (M=12).
//   w = exp(val - 12): exact softmax ratio, no online max/rescale machinery.
//   masked q rows: w = 1 for all k -> uniform weights (matches reference).
// PV: thread tile 4q x 4d, k split in halves across tx bit 3 (64 loads/kb).
// ---------------------------------------------------------------------------
__global__ __launch_bounds__(256) void moire_attn(
    const float* __restrict__ adj, const unsigned int* __restrict__ mask,
    const float* __restrict__ shifts, const float* __restrict__ widths,
    const float* __restrict__ slw, float* __restrict__ out)
{
    __shared__ float Qs[64][36];
    __shared__ float Ks[64][36];
    __shared__ float Vs[64][36];
    __shared__ float Ps[64][68];

    const int h  = blockIdx.x;   // fastest: adjacent blocks share adj tile (L2 reuse)
    const int qt = blockIdx.y;
    const int b  = blockIdx.z;
    const int q0 = qt * 64;
    const int tid = threadIdx.x;
    const int ty = tid >> 4, tx = tid & 15;
    const int d0 = (tx & 7) * 4;      // PV: 4 output dims
    const int khalf = tx >> 3;        // PV: k-range half

    const float sh   = shifts[h];
    const float invw = 1.0f / fmaxf(widths[h], 0.5f);
    const float sl   = slw[h];

    const float* Qg = g_qkv + (size_t)(((0 * 8 + b) * 8 + h) * 1024) * 32;
    const float* Kg = g_qkv + (size_t)(((1 * 8 + b) * 8 + h) * 1024) * 32;
    const float* Vg = g_qkv + (size_t)(((2 * 8 + b) * 8 + h) * 1024) * 32;

    // Q tile (float4), pre-scaled by 1/sqrt(32)
    #pragma unroll
    for (int i = tid; i < 64 * 8; i += 256) {
        int qi = i >> 3, d = (i & 7) * 4;
        float4 v = *(const float4*)&Qg[(q0 + qi) * 32 + d];
        v.x *= 0.17677669529663687f; v.y *= 0.17677669529663687f;
        v.z *= 0.17677669529663687f; v.w *= 0.17677669529663687f;
        *(float4*)&Qs[qi][d] = v;
    }

    bool mq[4];
    #pragma unroll
    for (int j = 0; j < 4; j++) mq[j] = (mask[b * 1024 + q0 + ty * 4 + j] != 0u);

    float lsum[4] = {0.f, 0.f, 0.f, 0.f};
    float acc[4][4] = {};

    for (int kb = 0; kb < 1024; kb += 64) {
        __syncthreads();  // previous PV done before overwriting tiles
        // K/V staging, float4
        #pragma unroll
        for (int i = tid; i < 64 * 8; i += 256) {
            int kj = i >> 3, d = (i & 7) * 4;
            *(float4*)&Ks[kj][d] = *(const float4*)&Kg[(kb + kj) * 32 + d];
            *(float4*)&Vs[kj][d] = *(const float4*)&Vg[(kb + kj) * 32 + d];
        }
        // adj + mask prefetch: thread's 4 k's are k = i*16 + tx (coalesced)
        float adjv[4][4];
        bool  mk[4];
        {
            const float* ab = adj + (size_t)(b * 1024 + q0 + ty * 4) * 1024 + kb + tx;
            #pragma unroll
            for (int i = 0; i < 4; i++) {
                #pragma unroll
                for (int j = 0; j < 4; j++)
                    adjv[j][i] = ab[(size_t)j * 1024 + i * 16];
                mk[i] = (mask[b * 1024 + kb + i * 16 + tx] != 0u);
            }
        }
        __syncthreads();  // tiles ready

        // 4x4 score microtile: dot over D=32, conflict-free K loads
        float s[4][4] = {};
        #pragma unroll
        for (int dd = 0; dd < 32; dd += 4) {
            float4 qv[4], kv[4];
            #pragma unroll
            for (int j = 0; j < 4; j++) qv[j] = *(const float4*)&Qs[ty * 4 + j][dd];
            #pragma unroll
            for (int i = 0; i < 4; i++) kv[i] = *(const float4*)&Ks[i * 16 + tx][dd];
            #pragma unroll
            for (int j = 0; j < 4; j++)
                #pragma unroll
                for (int i = 0; i < 4; i++)
                    s[j][i] += qv[j].x * kv[i].x + qv[j].y * kv[i].y +
                               qv[j].z * kv[i].z + qv[j].w * kv[i].w;
        }

        // moire + self-loop + mask + exp (static max M=12)
        const bool diag = (kb == q0);
        #pragma unroll
        for (int j = 0; j < 4; j++) {
            #pragma unroll
            for (int i = 0; i < 4; i++) {
                float t = adjv[j][i] - sh;
                float val = s[j][i] + fmaxf(-t * t * invw, -13.815510557964274f);
                if (diag && (ty * 4 + j == i * 16 + tx)) val += sl;
                float w = mq[j] ? (mk[i] ? __expf(val - 12.0f) : 0.0f) : 1.0f;
                lsum[j] += w;
                s[j][i] = w;
            }
        }

        // stage P as [k][q] (conflict-free)
        #pragma unroll
        for (int i = 0; i < 4; i++) {
            float4 p4 = make_float4(s[0][i], s[1][i], s[2][i], s[3][i]);
            *(float4*)&Ps[i * 16 + tx][ty * 4] = p4;
        }
        __syncthreads();  // P ready

        // PV: thread owns 4 queries x 4 dims over its 32-k half
        const int kbeg = khalf * 32;
        #pragma unroll 8
        for (int kj = kbeg; kj < kbeg + 32; kj++) {
            float4 p = *(const float4*)&Ps[kj][ty * 4];
            float4 v = *(const float4*)&Vs[kj][d0];
            acc[0][0] += p.x * v.x; acc[0][1] += p.x * v.y; acc[0][2] += p.x * v.z; acc[0][3] += p.x * v.w;
            acc[1][0] += p.y * v.x; acc[1][1] += p.y * v.y; acc[1][2] += p.y * v.z; acc[1][3] += p.y * v.w;
            acc[2][0] += p.z * v.x; acc[2][1] += p.z * v.y; acc[2][2] += p.z * v.z; acc[2][3] += p.z * v.w;
            acc[3][0] += p.w * v.x; acc[3][1] += p.w * v.y; acc[3][2] += p.w * v.z; acc[3][3] += p.w * v.w;
        }
    }

    // final l reduction over the 16 lanes of the ty group
    #pragma unroll
    for (int j = 0; j < 4; j++) {
        #pragma unroll
        for (int off = 8; off > 0; off >>= 1)
            lsum[j] += __shfl_xor_sync(0xffffffffu, lsum[j], off);
    }

    // combine k-halves through Qs (dead) and write out
    __syncthreads();
    if (khalf == 1) {
        #pragma unroll
        for (int j = 0; j < 4; j++)
            *(float4*)&Qs[ty * 4 + j][d0] =
                make_float4(acc[j][0], acc[j][1], acc[j][2], acc[j][3]);
    }
    __syncthreads();
    if (khalf == 0) {
        #pragma unroll
        for (int j = 0; j < 4; j++) {
            float4 o = *(const float4*)&Qs[ty * 4 + j][d0];
            float r = 1.0f / lsum[j];
            o.x = (o.x + acc[j][0]) * r;
            o.y = (o.y + acc[j][1]) * r;
            o.z = (o.z + acc[j][2]) * r;
            o.w = (o.w + acc[j][3]) * r;
            *(float4*)&out[(size_t)(b * 1024 + q0 + ty * 4 + j) * 256 + h * 32 + d0] = o;
        }
    }
}

// ---------------------------------------------------------------------------
// Launch. Inputs: x, adj, mask, W_qkv, b_qkv, shifts, widths, self_loop_w
// ---------------------------------------------------------------------------
extern "C" void kernel_launch(void* const* d_in, const int* in_sizes, int n_in,
                              void* d_out, int out_size)
{
    const float*        x      = (const float*)d_in[0];
    const float*        adj    = (const float*)d_in[1];
    const unsigned int* mask   = (const unsigned int*)d_in[2];
    const float*        W_qkv  = (const float*)d_in[3];
    const float*        b_qkv  = (const float*)d_in[4];
    const float*        shifts = (const float*)d_in[5];
    const float*        widths = (const float*)d_in[6];
    const float*        slw    = (const float*)d_in[7];
    float*              out    = (float*)d_out;

    qkv_gemm<<<dim3(12, 128), 256>>>(x, W_qkv, b_qkv);
    moire_attn<<<dim3(8, 16, 8), 256>>>(adj, mask, shifts, widths, slw, out);
}

// round 6
// speedup vs baseline: 1.7253x; 1.7253x over previous
#include <cuda_runtime.h>
#include <cuda_bf16.h>
#include <cstdint>

#define B_ 8
#define N_ 1024
#define H_ 8
#define D_ 32

// split-bf16 QKV scratch: [s][b][h][n][d], Q pre-scaled by 1/sqrt(D)
#define QKV_ELEMS (3u * B_ * H_ * N_ * D_)
__device__ __nv_bfloat16 g_hi[QKV_ELEMS];
__device__ __nv_bfloat16 g_lo[QKV_ELEMS];

// ---------------------------------------------------------------------------
// PTX helpers
// ---------------------------------------------------------------------------
__device__ __forceinline__ uint32_t sptr(const void* p) {
    return (uint32_t)__cvta_generic_to_shared(p);
}
__device__ __forceinline__ void ldmx4(uint32_t* r, uint32_t a) {
    asm volatile("ldmatrix.sync.aligned.m8n8.x4.shared.b16 {%0,%1,%2,%3}, [%4];"
                 : "=r"(r[0]), "=r"(r[1]), "=r"(r[2]), "=r"(r[3]) : "r"(a));
}
__device__ __forceinline__ void ldmx2(uint32_t* r, uint32_t a) {
    asm volatile("ldmatrix.sync.aligned.m8n8.x2.shared.b16 {%0,%1}, [%2];"
                 : "=r"(r[0]), "=r"(r[1]) : "r"(a));
}
__device__ __forceinline__ void ldmx2t(uint32_t* r, uint32_t a) {
    asm volatile("ldmatrix.sync.aligned.m8n8.x2.trans.shared.b16 {%0,%1}, [%2];"
                 : "=r"(r[0]), "=r"(r[1]) : "r"(a));
}
__device__ __forceinline__ void mma_bf16(float* d, const uint32_t* a, const uint32_t* b) {
    asm volatile("mma.sync.aligned.m16n8k16.row.col.f32.bf16.bf16.f32 "
                 "{%0,%1,%2,%3}, {%4,%5,%6,%7}, {%8,%9}, {%0,%1,%2,%3};"
                 : "+f"(d[0]), "+f"(d[1]), "+f"(d[2]), "+f"(d[3])
                 : "r"(a[0]), "r"(a[1]), "r"(a[2]), "r"(a[3]), "r"(b[0]), "r"(b[1]));
}
// pack two fp32 -> bf16x2 (first arg -> low half)
__device__ __forceinline__ uint32_t packbf(float lo, float hi) {
    uint32_t r;
    asm("cvt.rn.bf16x2.f32 %0, %1, %2;" : "=r"(r) : "f"(hi), "f"(lo));
    return r;
}
__device__ __forceinline__ float2 bf2f(uint32_t u) {
    __nv_bfloat162 t = *reinterpret_cast<__nv_bfloat162*>(&u);
    return __bfloat1622float2(t);
}

// ---------------------------------------------------------------------------
// Kernel 1: QKV projection, fp32 compute, split-bf16 epilogue (Q pre-scaled).
// ---------------------------------------------------------------------------
__global__ __launch_bounds__(256) void qkv_gemm(
    const float* __restrict__ x, const float* __restrict__ W,
    const float* __restrict__ bias)
{
    __shared__ float As[64][33];
    __shared__ float Bs[32][64];

    const int tid = threadIdx.x;
    const int ty = tid >> 4, tx = tid & 15;
    const int rb = blockIdx.y * 64;
    const int cb = blockIdx.x * 64;

    float c[4][4] = {};

    for (int k0 = 0; k0 < 256; k0 += 32) {
        #pragma unroll
        for (int i = tid; i < 64 * 32; i += 256) {
            int r = i >> 5, k = i & 31;
            As[r][k] = x[(rb + r) * 256 + k0 + k];
        }
        #pragma unroll
        for (int i = tid; i < 32 * 64; i += 256) {
            int k = i >> 6, cc = i & 63;
            Bs[k][cc] = W[(k0 + k) * 768 + cb + cc];
        }
        __syncthreads();

        #pragma unroll
        for (int kk = 0; kk < 32; kk++) {
            float a0 = As[ty * 4 + 0][kk];
            float a1 = As[ty * 4 + 1][kk];
            float a2 = As[ty * 4 + 2][kk];
            float a3 = As[ty * 4 + 3][kk];
            float4 bv = *(const float4*)&Bs[kk][tx * 4];
            c[0][0] += a0 * bv.x; c[0][1] += a0 * bv.y; c[0][2] += a0 * bv.z; c[0][3] += a0 * bv.w;
            c[1][0] += a1 * bv.x; c[1][1] += a1 * bv.y; c[1][2] += a1 * bv.z; c[1][3] += a1 * bv.w;
            c[2][0] += a2 * bv.x; c[2][1] += a2 * bv.y; c[2][2] += a2 * bv.z; c[2][3] += a2 * bv.w;
            c[3][0] += a3 * bv.x; c[3][1] += a3 * bv.y; c[3][2] += a3 * bv.z; c[3][3] += a3 * bv.w;
        }
        __syncthreads();
    }

    const int c0  = cb + tx * 4;
    const int s   = c0 >> 8;
    const int rem = c0 & 255;
    const int h   = rem >> 5;
    const int d   = rem & 31;
    float4 bb = *(const float4*)&bias[c0];
    const float sc = (s == 0) ? 0.17677669529663687f : 1.0f;

    #pragma unroll
    for (int j = 0; j < 4; j++) {
        int r = rb + ty * 4 + j;
        int bq = r >> 10, n = r & 1023;
        float v0 = (c[j][0] + bb.x) * sc;
        float v1 = (c[j][1] + bb.y) * sc;
        float v2 = (c[j][2] + bb.z) * sc;
        float v3 = (c[j][3] + bb.w) * sc;
        uint32_t h01 = packbf(v0, v1);
        uint32_t h23 = packbf(v2, v3);
        float2 f01 = bf2f(h01), f23 = bf2f(h23);
        uint32_t l01 = packbf(v0 - f01.x, v1 - f01.y);
        uint32_t l23 = packbf(v2 - f23.x, v3 - f23.y);
        size_t idx = ((size_t)((s * 8 + bq) * 8 + h) * 1024 + n) * 32 + d;
        *(uint2*)&g_hi[idx] = make_uint2(h01, h23);
        *(uint2*)&g_lo[idx] = make_uint2(l01, l23);
    }
}

// ---------------------------------------------------------------------------
// Kernel 2: tensor-core moire attention.
// Block = (h, 64-q tile, b), 8 warps: warp grid 4(m16 rows) x 2(32-key slice).
// QK: split-bf16 (3 MMAs). PV: split-P x split-V (3 MMAs) -> ~2^-16 accuracy.
// Static-max softmax w = exp(val - 12); masked-q rows w = 1 (uniform).
// ---------------------------------------------------------------------------
__global__ __launch_bounds__(256) void moire_attn(
    const float* __restrict__ adj, const unsigned int* __restrict__ mask,
    const float* __restrict__ shifts, const float* __restrict__ widths,
    const float* __restrict__ slw, float* __restrict__ out)
{
    // manual smem layout (Obuf overlays Qh/Ql after the main loop)
    __shared__ __align__(16) unsigned char smraw[64 * 40 * 2 * 6 + 64 * 4 + 64 * 4];
    __nv_bfloat16* Qh = (__nv_bfloat16*)(smraw);
    __nv_bfloat16* Ql = (__nv_bfloat16*)(smraw + 5120);
    __nv_bfloat16* Kh = (__nv_bfloat16*)(smraw + 10240);
    __nv_bfloat16* Kl = (__nv_bfloat16*)(smraw + 15360);
    __nv_bfloat16* Vh = (__nv_bfloat16*)(smraw + 20480);
    __nv_bfloat16* Vl = (__nv_bfloat16*)(smraw + 25600);
    float*         lsum = (float*)(smraw + 30720);
    unsigned int*  mks  = (unsigned int*)(smraw + 30976);

    const int hh = blockIdx.x;
    const int q0 = blockIdx.y * 64;
    const int bb = blockIdx.z;
    const int tid = threadIdx.x;
    const int w   = tid >> 5;
    const int l   = tid & 31;
    const int wm  = w & 3;          // m-tile: rows 16*wm
    const int wk  = w >> 2;         // key slice: cols 32*wk
    const int m0  = 16 * wm;
    const int n0k = 32 * wk;
    const int l16 = l & 15;
    const int qal = m0 + (l >> 2);  // local q row (upper)
    const int qbl = qal + 8;        // local q row (lower)

    const float sh   = shifts[hh];
    const float invw = 1.0f / fmaxf(widths[hh], 0.5f);
    const float sl   = slw[hh];
    const float LOGEPS = -13.815510557964274f;

    const size_t qbase = ((size_t)((0 * 8 + bb) * 8 + hh)) * 1024 * 32;
    const size_t kbase = ((size_t)((1 * 8 + bb) * 8 + hh)) * 1024 * 32;
    const size_t vbase = ((size_t)((2 * 8 + bb) * 8 + hh)) * 1024 * 32;

    // ---- stage Q tile (hi/lo), zero lsum ----
    {
        int row = tid >> 2, part = tid & 3;
        size_t gq = qbase + (size_t)(q0 + row) * 32 + part * 8;
        *(uint4*)(Qh + row * 40 + part * 8) = *(const uint4*)(g_hi + gq);
        *(uint4*)(Ql + row * 40 + part * 8) = *(const uint4*)(g_lo + gq);
        if (tid < 64) lsum[tid] = 0.0f;
    }
    const bool mqa = (mask[(size_t)bb * 1024 + q0 + qal] != 0u);
    const bool mqb = (mask[(size_t)bb * 1024 + q0 + qbl] != 0u);
    __syncthreads();

    // ---- Q fragments (held in registers for the whole kernel) ----
    uint32_t qfh[2][4], qfl[2][4];
    #pragma unroll
    for (int ks = 0; ks < 2; ks++) {
        int d0 = ks * 16;
        int off = (m0 + (l & 15)) * 40 + d0 + ((l & 16) >> 1);
        ldmx4(qfh[ks], sptr(Qh + off));
        ldmx4(qfl[ks], sptr(Ql + off));
    }

    float Oacc[4][4] = {};
    float lsa = 0.0f, lsb = 0.0f;

    for (int kb = 0; kb < 1024; kb += 64) {
        __syncthreads();  // previous iter's ldmatrix reads done
        {
            int row = tid >> 2, part = tid & 3;
            size_t gk = kbase + (size_t)(kb + row) * 32 + part * 8;
            size_t gv = vbase + (size_t)(kb + row) * 32 + part * 8;
            *(uint4*)(Kh + row * 40 + part * 8) = *(const uint4*)(g_hi + gk);
            *(uint4*)(Kl + row * 40 + part * 8) = *(const uint4*)(g_lo + gk);
            *(uint4*)(Vh + row * 40 + part * 8) = *(const uint4*)(g_hi + gv);
            *(uint4*)(Vl + row * 40 + part * 8) = *(const uint4*)(g_lo + gv);
            if (tid < 16)
                ((uint4*)mks)[tid] = *(const uint4*)(mask + (size_t)bb * 1024 + kb + tid * 4);
        }
        // adj prefetch (fragment layout; 32B-coalesced float2 per lane quad)
        float2 av[2][4];
        {
            const float* ap = adj + ((size_t)(bb * 1024 + q0 + qal)) * 1024
                              + kb + n0k + 2 * (l & 3);
            #pragma unroll
            for (int t = 0; t < 4; t++) {
                av[0][t] = *(const float2*)(ap + 8 * t);
                av[1][t] = *(const float2*)(ap + 8 * 1024 + 8 * t);
            }
        }
        __syncthreads();  // tiles ready

        // ---- QK: S[16 x 32] in 4 n8-tile accumulators, split-bf16 ----
        float acc[4][4] = {};
        #pragma unroll
        for (int ks = 0; ks < 2; ks++) {
            int d0 = ks * 16;
            #pragma unroll
            for (int t = 0; t < 4; t++) {
                int koff = (n0k + 8 * t + (l16 & 7)) * 40 + d0 + (l16 & 8);
                uint32_t bh[2], bl[2];
                ldmx2(bh, sptr(Kh + koff));
                ldmx2(bl, sptr(Kl + koff));
                mma_bf16(acc[t], qfh[ks], bh);
                mma_bf16(acc[t], qfl[ks], bh);
                mma_bf16(acc[t], qfh[ks], bl);
            }
        }

        // ---- elementwise: moire + self-loop + mask + exp(val-12) ----
        const bool diag = (kb == q0);
        #pragma unroll
        for (int t = 0; t < 4; t++) {
            int c0 = n0k + 8 * t + 2 * (l & 3);
            bool mk0 = (mks[c0] != 0u), mk1 = (mks[c0 + 1] != 0u);
            float ax = av[0][t].x - sh, ay = av[0][t].y - sh;
            float bx = av[1][t].x - sh, by = av[1][t].y - sh;
            float v00 = acc[t][0] + fmaxf(-ax * ax * invw, LOGEPS);
            float v01 = acc[t][1] + fmaxf(-ay * ay * invw, LOGEPS);
            float v10 = acc[t][2] + fmaxf(-bx * bx * invw, LOGEPS);
            float v11 = acc[t][3] + fmaxf(-by * by * invw, LOGEPS);
            if (diag) {
                if (qal == c0)     v00 += sl;
                if (qal == c0 + 1) v01 += sl;
                if (qbl == c0)     v10 += sl;
                if (qbl == c0 + 1) v11 += sl;
            }
            float w00 = mqa ? (mk0 ? __expf(v00 - 12.0f) : 0.0f) : 1.0f;
            float w01 = mqa ? (mk1 ? __expf(v01 - 12.0f) : 0.0f) : 1.0f;
            float w10 = mqb ? (mk0 ? __expf(v10 - 12.0f) : 0.0f) : 1.0f;
            float w11 = mqb ? (mk1 ? __expf(v11 - 12.0f) : 0.0f) : 1.0f;
            lsa += w00 + w01;
            lsb += w10 + w11;
            acc[t][0] = w00; acc[t][1] = w01; acc[t][2] = w10; acc[t][3] = w11;
        }

        // ---- P fragments: accumulator layout == A-fragment layout ----
        uint32_t pfh[2][4], pfl[2][4];
        #pragma unroll
        for (int cch = 0; cch < 2; cch++) {
            #pragma unroll
            for (int rr = 0; rr < 2; rr++) {          // rr=0: tile 2c, rr=1: tile 2c+1
                const float* a4 = acc[2 * cch + rr];
                uint32_t u0 = packbf(a4[0], a4[1]);   // row qa pair
                uint32_t u1 = packbf(a4[2], a4[3]);   // row qb pair
                float2 f0 = bf2f(u0), f1 = bf2f(u1);
                pfh[cch][rr * 2 + 0] = u0;            // a0/a2
                pfh[cch][rr * 2 + 1] = u1;            // a1/a3
                pfl[cch][rr * 2 + 0] = packbf(a4[0] - f0.x, a4[1] - f0.y);
                pfl[cch][rr * 2 + 1] = packbf(a4[2] - f1.x, a4[3] - f1.y);
            }
        }

        // ---- PV: O += Ph@Vh + Pl@Vh + Ph@Vl ----
        #pragma unroll
        for (int cch = 0; cch < 2; cch++) {
            #pragma unroll
            for (int td = 0; td < 4; td++) {
                int voff = (n0k + 16 * cch + l16) * 40 + 8 * td;
                uint32_t vbh[2], vbl[2];
                ldmx2t(vbh, sptr(Vh + voff));
                ldmx2t(vbl, sptr(Vl + voff));
                mma_bf16(Oacc[td], pfh[cch], vbh);
                mma_bf16(Oacc[td], pfl[cch], vbh);
                mma_bf16(Oacc[td], pfh[cch], vbl);
            }
        }
    }

    // ---- lsum reduction: lanes %4 share a row ----
    lsa += __shfl_xor_sync(0xffffffffu, lsa, 1);
    lsa += __shfl_xor_sync(0xffffffffu, lsa, 2);
    lsb += __shfl_xor_sync(0xffffffffu, lsb, 1);
    lsb += __shfl_xor_sync(0xffffffffu, lsb, 2);
    if ((l & 3) == 0) {
        atomicAdd(&lsum[qal], lsa);
        atomicAdd(&lsum[qbl], lsb);
    }
    __syncthreads();

    // ---- combine wk halves via Obuf (overlays Qh/Ql) and write out ----
    float* Obuf = (float*)smraw;  // 64 x 32 floats = 8KB
    if (wk == 1) {
        #pragma unroll
        for (int td = 0; td < 4; td++) {
            int n = 8 * td + 2 * (l & 3);
            *(float2*)&Obuf[qal * 32 + n] = make_float2(Oacc[td][0], Oacc[td][1]);
            *(float2*)&Obuf[qbl * 32 + n] = make_float2(Oacc[td][2], Oacc[td][3]);
        }
    }
    __syncthreads();
    if (wk == 0) {
        float rla = 1.0f / lsum[qal];
        float rlb = 1.0f / lsum[qbl];
        #pragma unroll
        for (int td = 0; td < 4; td++) {
            int n = 8 * td + 2 * (l & 3);
            float2 oa = *(const float2*)&Obuf[qal * 32 + n];
            float2 ob = *(const float2*)&Obuf[qbl * 32 + n];
            oa.x = (oa.x + Oacc[td][0]) * rla;
            oa.y = (oa.y + Oacc[td][1]) * rla;
            ob.x = (ob.x + Oacc[td][2]) * rlb;
            ob.y = (ob.y + Oacc[td][3]) * rlb;
            *(float2*)&out[((size_t)bb * 1024 + q0 + qal) * 256 + hh * 32 + n] = oa;
            *(float2*)&out[((size_t)bb * 1024 + q0 + qbl) * 256 + hh * 32 + n] = ob;
        }
    }
}

// ---------------------------------------------------------------------------
// Launch. Inputs: x, adj, mask, W_qkv, b_qkv, shifts, widths, self_loop_w
// ---------------------------------------------------------------------------
extern "C" void kernel_launch(void* const* d_in, const int* in_sizes, int n_in,
                              void* d_out, int out_size)
{
    const float*        x      = (const float*)d_in[0];
    const float*        adj    = (const float*)d_in[1];
    const unsigned int* mask   = (const unsigned int*)d_in[2];
    const float*        W_qkv  = (const float*)d_in[3];
    const float*        b_qkv  = (const float*)d_in[4];
    const float*        shifts = (const float*)d_in[5];
    const float*        widths = (const float*)d_in[6];
    const float*        slw    = (const float*)d_in[7];
    float*              out    = (float*)d_out;

    qkv_gemm<<<dim3(12, 128), 256>>>(x, W_qkv, b_qkv);
    moire_attn<<<dim3(8, 16, 8), 256>>>(adj, mask, shifts, widths, slw, out);
}

// round 7
// speedup vs baseline: 2.2454x; 1.3014x over previous
#include <cuda_runtime.h>
#include <cuda_bf16.h>
#include <cstdint>

#define B_ 8
#define N_ 1024
#define H_ 8
#define D_ 32
#define XN (8192 * 256)
#define WN (256 * 768)

// split-bf16 QKV scratch: [s][b][h][n][d], Q pre-scaled by 1/sqrt(D)
#define QKV_ELEMS (3u * B_ * H_ * N_ * D_)
__device__ __nv_bfloat16 g_hi[QKV_ELEMS];
__device__ __nv_bfloat16 g_lo[QKV_ELEMS];
// split-bf16 GEMM operands
__device__ __nv_bfloat16 g_xh[XN], g_xl[XN];
__device__ __nv_bfloat16 g_wh[WN], g_wl[WN];

// ---------------------------------------------------------------------------
// PTX helpers
// ---------------------------------------------------------------------------
__device__ __forceinline__ uint32_t sptr(const void* p) {
    return (uint32_t)__cvta_generic_to_shared(p);
}
__device__ __forceinline__ void ldmx4(uint32_t* r, uint32_t a) {
    asm volatile("ldmatrix.sync.aligned.m8n8.x4.shared.b16 {%0,%1,%2,%3}, [%4];"
                 : "=r"(r[0]), "=r"(r[1]), "=r"(r[2]), "=r"(r[3]) : "r"(a));
}
__device__ __forceinline__ void ldmx2t(uint32_t* r, uint32_t a) {
    asm volatile("ldmatrix.sync.aligned.m8n8.x2.trans.shared.b16 {%0,%1}, [%2];"
                 : "=r"(r[0]), "=r"(r[1]) : "r"(a));
}
__device__ __forceinline__ void mma_bf16(float* d, const uint32_t* a,
                                         uint32_t b0, uint32_t b1) {
    asm volatile("mma.sync.aligned.m16n8k16.row.col.f32.bf16.bf16.f32 "
                 "{%0,%1,%2,%3}, {%4,%5,%6,%7}, {%8,%9}, {%0,%1,%2,%3};"
                 : "+f"(d[0]), "+f"(d[1]), "+f"(d[2]), "+f"(d[3])
                 : "r"(a[0]), "r"(a[1]), "r"(a[2]), "r"(a[3]), "r"(b0), "r"(b1));
}
// pack two fp32 -> bf16x2 (first arg -> low half) — convention proven in R5
__device__ __forceinline__ uint32_t packbf(float lo, float hi) {
    uint32_t r;
    asm("cvt.rn.bf16x2.f32 %0, %1, %2;" : "=r"(r) : "f"(hi), "f"(lo));
    return r;
}
__device__ __forceinline__ float2 bf2f(uint32_t u) {
    __nv_bfloat162 t = *reinterpret_cast<__nv_bfloat162*>(&u);
    return __bfloat1622float2(t);
}
__device__ __forceinline__ void cpa16(uint32_t dst, const void* src) {
    asm volatile("cp.async.cg.shared.global [%0], [%1], 16;" :: "r"(dst), "l"(src));
}
#define CP_COMMIT asm volatile("cp.async.commit_group;")
#define CP_WAIT0  asm volatile("cp.async.wait_group 0;")
#define CP_WAIT1  asm volatile("cp.async.wait_group 1;")

// ---------------------------------------------------------------------------
// Kernel 0: split x and W into bf16 hi/lo.
// ---------------------------------------------------------------------------
__global__ __launch_bounds__(256) void split_xw(
    const float* __restrict__ x, const float* __restrict__ W)
{
    int i4 = (blockIdx.x * 256 + threadIdx.x) * 4;
    const float* src;
    __nv_bfloat16 *dh, *dl;
    int off;
    if (i4 < XN) {
        src = x; dh = g_xh; dl = g_xl; off = i4;
    } else {
        off = i4 - XN;
        if (off >= WN) return;
        src = W; dh = g_wh; dl = g_wl;
    }
    float4 v = *(const float4*)(src + off);
    uint32_t h01 = packbf(v.x, v.y), h23 = packbf(v.z, v.w);
    float2 f01 = bf2f(h01), f23 = bf2f(h23);
    *(uint2*)&dh[off] = make_uint2(h01, h23);
    *(uint2*)&dl[off] = make_uint2(packbf(v.x - f01.x, v.y - f01.y),
                                   packbf(v.z - f23.x, v.w - f23.y));
}

// ---------------------------------------------------------------------------
// Kernel 1: QKV projection via split-bf16 MMA, cp.async 2-stage pipeline.
// Block tile M=64 N=64, K chunks of 32 (8 chunks). 8 warps = 2m x 4n.
// Epilogue: +bias, Q-scale, re-split to hi/lo, scatter to [s][b][h][n][d].
// ---------------------------------------------------------------------------
__global__ __launch_bounds__(256) void qkv_gemm_mma(const float* __restrict__ bias)
{
    // stage: xh 64x40(5120B), xl 5120, wh 32x72(4608B), wl 4608 -> 19456B
    __shared__ __align__(16) unsigned char sm[2 * 19456];
    const int tid = threadIdx.x;
    const int w = tid >> 5, l = tid & 31;
    const int l16 = l & 15;
    const int mw = 32 * (w & 1);
    const int nw = 16 * (w >> 1);
    const int rb = blockIdx.y * 64;
    const int cb = blockIdx.x * 64;

    const int xrow = tid >> 2, xpart = tid & 3;
    const int wrow = tid >> 3, wpart = tid & 7;

    auto stage = [&](int k0, unsigned char* buf) {
        cpa16(sptr(buf + xrow * 80 + xpart * 16),
              g_xh + (size_t)(rb + xrow) * 256 + k0 + xpart * 8);
        cpa16(sptr(buf + 5120 + xrow * 80 + xpart * 16),
              g_xl + (size_t)(rb + xrow) * 256 + k0 + xpart * 8);
        cpa16(sptr(buf + 10240 + wrow * 144 + wpart * 16),
              g_wh + (size_t)(k0 + wrow) * 768 + cb + wpart * 8);
        cpa16(sptr(buf + 14848 + wrow * 144 + wpart * 16),
              g_wl + (size_t)(k0 + wrow) * 768 + cb + wpart * 8);
    };

    float acc[2][2][4] = {};

    stage(0, sm);
    CP_COMMIT;

    for (int c = 0; c < 8; c++) {
        unsigned char* buf = sm + (c & 1) * 19456;
        if (c < 7) {
            stage((c + 1) * 32, sm + ((c + 1) & 1) * 19456);
            CP_COMMIT;
            CP_WAIT1;
        } else {
            CP_WAIT0;
        }
        __syncthreads();

        const __nv_bfloat16* xh = (const __nv_bfloat16*)(buf);
        const __nv_bfloat16* xl = (const __nv_bfloat16*)(buf + 5120);
        const __nv_bfloat16* wh = (const __nv_bfloat16*)(buf + 10240);
        const __nv_bfloat16* wl = (const __nv_bfloat16*)(buf + 14848);

        #pragma unroll
        for (int ks = 0; ks < 2; ks++) {
            uint32_t ah[2][4], al[2][4];
            #pragma unroll
            for (int mf = 0; mf < 2; mf++) {
                int aoff = (mw + 16 * mf + l16) * 40 + ks * 16 + ((l & 16) >> 1);
                ldmx4(ah[mf], sptr(xh + aoff));
                ldmx4(al[mf], sptr(xl + aoff));
            }
            #pragma unroll
            for (int t = 0; t < 2; t++) {
                int woff = (ks * 16 + l16) * 72 + nw + 8 * t;
                uint32_t bh[2], bl[2];
                ldmx2t(bh, sptr(wh + woff));
                ldmx2t(bl, sptr(wl + woff));
                #pragma unroll
                for (int mf = 0; mf < 2; mf++) {
                    mma_bf16(acc[mf][t], ah[mf], bh[0], bh[1]);
                    mma_bf16(acc[mf][t], al[mf], bh[0], bh[1]);
                    mma_bf16(acc[mf][t], ah[mf], bl[0], bl[1]);
                }
            }
        }
        __syncthreads();
    }

    #pragma unroll
    for (int t = 0; t < 2; t++) {
        int c0 = cb + nw + 8 * t + 2 * (l & 3);
        int s = c0 >> 8, rem = c0 & 255, h = rem >> 5, d = rem & 31;
        float sc = (s == 0) ? 0.17677669529663687f : 1.0f;
        float b0 = bias[c0], b1 = bias[c0 + 1];
        #pragma unroll
        for (int mf = 0; mf < 2; mf++) {
            #pragma unroll
            for (int rr = 0; rr < 2; rr++) {
                int r = rb + mw + 16 * mf + (l >> 2) + 8 * rr;
                int bq = r >> 10, n = r & 1023;
                float v0 = (acc[mf][t][2 * rr + 0] + b0) * sc;
                float v1 = (acc[mf][t][2 * rr + 1] + b1) * sc;
                uint32_t hv = packbf(v0, v1);
                float2 f = bf2f(hv);
                uint32_t lv = packbf(v0 - f.x, v1 - f.y);
                size_t idx = ((size_t)((s * 8 + bq) * 8 + h) * 1024 + n) * 32 + d;
                *(uint32_t*)&g_hi[idx] = hv;
                *(uint32_t*)&g_lo[idx] = lv;
            }
        }
    }
}

// ---------------------------------------------------------------------------
// Kernel 2: tensor-core moire attention, cp.async 2-stage K/V pipeline.
// QK: split-bf16 (3 MMAs), K fragments via ldmatrix.x4 (2 tiles/load).
// PV: split-P x split-V (3 MMAs). Static-max softmax w = exp(val - 12).
// ---------------------------------------------------------------------------
__global__ __launch_bounds__(256, 2) void moire_attn(
    const float* __restrict__ adj, const unsigned int* __restrict__ mask,
    const float* __restrict__ shifts, const float* __restrict__ widths,
    const float* __restrict__ slw, float* __restrict__ out)
{
    // [0,4096) Qh  [4096,8192) Ql  (pitch 32 bf16; Obuf overlays after loop)
    // [8192, 8192+2*20480): two K/V stages {Kh,Kl,Vh,Vl} pitch 40 bf16
    // lsum overlays stage area (used only after the loop)
    __shared__ __align__(16) unsigned char smraw[8192 + 2 * 20480];

    const int hh = blockIdx.x;
    const int q0 = blockIdx.y * 64;
    const int bb = blockIdx.z;
    const int tid = threadIdx.x;
    const int w   = tid >> 5;
    const int l   = tid & 31;
    const int wm  = w & 3;
    const int wk  = w >> 2;
    const int m0  = 16 * wm;
    const int n0k = 32 * wk;
    const int l16 = l & 15;
    const int qal = m0 + (l >> 2);
    const int qbl = qal + 8;

    const float sh   = shifts[hh];
    const float invw = 1.0f / fmaxf(widths[hh], 0.5f);
    const float sl   = slw[hh];
    const float LOGEPS = -13.815510557964274f;

    const size_t qbase = ((size_t)((0 * 8 + bb) * 8 + hh)) * 1024 * 32;
    const size_t kbase = ((size_t)((1 * 8 + bb) * 8 + hh)) * 1024 * 32;
    const size_t vbase = ((size_t)((2 * 8 + bb) * 8 + hh)) * 1024 * 32;

    __nv_bfloat16* Qh = (__nv_bfloat16*)(smraw);
    __nv_bfloat16* Ql = (__nv_bfloat16*)(smraw + 4096);

    const int row = tid >> 2, part = tid & 3;

    auto stageKV = [&](int kb, unsigned char* buf) {
        size_t gk = kbase + (size_t)(kb + row) * 32 + part * 8;
        size_t gv = vbase + (size_t)(kb + row) * 32 + part * 8;
        cpa16(sptr(buf + row * 80 + part * 16),         g_hi + gk);
        cpa16(sptr(buf + 5120 + row * 80 + part * 16),  g_lo + gk);
        cpa16(sptr(buf + 10240 + row * 80 + part * 16), g_hi + gv);
        cpa16(sptr(buf + 15360 + row * 80 + part * 16), g_lo + gv);
    };

    // stage Q (plain LDG) + prefetch stage 0 K/V (cp.async)
    {
        size_t gq = qbase + (size_t)(q0 + row) * 32 + part * 8;
        *(uint4*)(Qh + row * 32 + part * 8) = *(const uint4*)(g_hi + gq);
        *(uint4*)(Ql + row * 32 + part * 8) = *(const uint4*)(g_lo + gq);
    }
    stageKV(0, smraw + 8192);
    CP_COMMIT;

    const bool mqa = (mask[(size_t)bb * 1024 + q0 + qal] != 0u);
    const bool mqb = (mask[(size_t)bb * 1024 + q0 + qbl] != 0u);
    __syncthreads();

    uint32_t qfh[2][4], qfl[2][4];
    #pragma unroll
    for (int ks = 0; ks < 2; ks++) {
        int off = (m0 + l16) * 32 + ks * 16 + ((l & 16) >> 1);
        ldmx4(qfh[ks], sptr(Qh + off));
        ldmx4(qfl[ks], sptr(Ql + off));
    }

    float Oacc[4][4] = {};
    float lsa = 0.0f, lsb = 0.0f;

    for (int it = 0; it < 16; it++) {
        const int kb = it * 64;
        if (it < 15) {
            stageKV(kb + 64, smraw + 8192 + ((it + 1) & 1) * 20480);
            CP_COMMIT;
        }
        // adj + mask prefetch (regs; overlaps the cp.async wait)
        float2 av[2][4];
        uint2  mkp[4];
        {
            const float* ap = adj + ((size_t)(bb * 1024 + q0 + qal)) * 1024
                              + kb + n0k + 2 * (l & 3);
            const unsigned int* mp = mask + (size_t)bb * 1024 + kb + n0k + 2 * (l & 3);
            #pragma unroll
            for (int t = 0; t < 4; t++) {
                av[0][t] = *(const float2*)(ap + 8 * t);
                av[1][t] = *(const float2*)(ap + 8 * 1024 + 8 * t);
                mkp[t]   = *(const uint2*)(mp + 8 * t);
            }
        }
        if (it < 15) { CP_WAIT1; } else { CP_WAIT0; }
        __syncthreads();

        unsigned char* buf = smraw + 8192 + (it & 1) * 20480;
        const __nv_bfloat16* Kh = (const __nv_bfloat16*)(buf);
        const __nv_bfloat16* Kl = (const __nv_bfloat16*)(buf + 5120);
        const __nv_bfloat16* Vh = (const __nv_bfloat16*)(buf + 10240);
        const __nv_bfloat16* Vl = (const __nv_bfloat16*)(buf + 15360);

        // ---- QK: 4 n8-tile accumulators; K B-frags via ldmatrix.x4 ----
        float acc[4][4] = {};
        #pragma unroll
        for (int ks = 0; ks < 2; ks++) {
            #pragma unroll
            for (int t2 = 0; t2 < 2; t2++) {
                int koff = (n0k + 16 * t2 + l16) * 40 + ks * 16 + ((l & 16) >> 1);
                uint32_t rh[4], rl[4];
                ldmx4(rh, sptr(Kh + koff));
                ldmx4(rl, sptr(Kl + koff));
                mma_bf16(acc[2 * t2],     qfh[ks], rh[0], rh[2]);
                mma_bf16(acc[2 * t2],     qfl[ks], rh[0], rh[2]);
                mma_bf16(acc[2 * t2],     qfh[ks], rl[0], rl[2]);
                mma_bf16(acc[2 * t2 + 1], qfh[ks], rh[1], rh[3]);
                mma_bf16(acc[2 * t2 + 1], qfl[ks], rh[1], rh[3]);
                mma_bf16(acc[2 * t2 + 1], qfh[ks], rl[1], rl[3]);
            }
        }

        // ---- elementwise: moire + self-loop + mask + exp(val-12) ----
        const bool diag = (kb == q0);
        #pragma unroll
        for (int t = 0; t < 4; t++) {
            int c0 = n0k + 8 * t + 2 * (l & 3);
            bool mk0 = (mkp[t].x != 0u), mk1 = (mkp[t].y != 0u);
            float ax = av[0][t].x - sh, ay = av[0][t].y - sh;
            float bx = av[1][t].x - sh, by = av[1][t].y - sh;
            float v00 = acc[t][0] + fmaxf(-ax * ax * invw, LOGEPS);
            float v01 = acc[t][1] + fmaxf(-ay * ay * invw, LOGEPS);
            float v10 = acc[t][2] + fmaxf(-bx * bx * invw, LOGEPS);
            float v11 = acc[t][3] + fmaxf(-by * by * invw, LOGEPS);
            if (diag) {
                if (qal == c0)     v00 += sl;
                if (qal == c0 + 1) v01 += sl;
                if (qbl == c0)     v10 += sl;
                if (qbl == c0 + 1) v11 += sl;
            }
            float w00 = mqa ? (mk0 ? __expf(v00 - 12.0f) : 0.0f) : 1.0f;
            float w01 = mqa ? (mk1 ? __expf(v01 - 12.0f) : 0.0f) : 1.0f;
            float w10 = mqb ? (mk0 ? __expf(v10 - 12.0f) : 0.0f) : 1.0f;
            float w11 = mqb ? (mk1 ? __expf(v11 - 12.0f) : 0.0f) : 1.0f;
            lsa += w00 + w01;
            lsb += w10 + w11;
            acc[t][0] = w00; acc[t][1] = w01; acc[t][2] = w10; acc[t][3] = w11;
        }

        // ---- P fragments (accumulator layout == A-fragment layout) ----
        uint32_t pfh[2][4], pfl[2][4];
        #pragma unroll
        for (int cch = 0; cch < 2; cch++) {
            #pragma unroll
            for (int rr = 0; rr < 2; rr++) {
                const float* a4 = acc[2 * cch + rr];
                uint32_t u0 = packbf(a4[0], a4[1]);
                uint32_t u1 = packbf(a4[2], a4[3]);
                float2 f0 = bf2f(u0), f1 = bf2f(u1);
                pfh[cch][rr * 2 + 0] = u0;
                pfh[cch][rr * 2 + 1] = u1;
                pfl[cch][rr * 2 + 0] = packbf(a4[0] - f0.x, a4[1] - f0.y);
                pfl[cch][rr * 2 + 1] = packbf(a4[2] - f1.x, a4[3] - f1.y);
            }
        }

        // ---- PV: O += Ph@Vh + Pl@Vh + Ph@Vl ----
        #pragma unroll
        for (int cch = 0; cch < 2; cch++) {
            #pragma unroll
            for (int td = 0; td < 4; td++) {
                int voff = (n0k + 16 * cch + l16) * 40 + 8 * td;
                uint32_t vbh[2], vbl[2];
                ldmx2t(vbh, sptr(Vh + voff));
                ldmx2t(vbl, sptr(Vl + voff));
                mma_bf16(Oacc[td], pfh[cch], vbh[0], vbh[1]);
                mma_bf16(Oacc[td], pfl[cch], vbh[0], vbh[1]);
                mma_bf16(Oacc[td], pfh[cch], vbl[0], vbl[1]);
            }
        }
        __syncthreads();
    }

    // ---- lsum: zero (overlay on stage area), reduce, accumulate ----
    float* lsum = (float*)(smraw + 8192);
    if (tid < 64) lsum[tid] = 0.0f;
    __syncthreads();
    lsa += __shfl_xor_sync(0xffffffffu, lsa, 1);
    lsa += __shfl_xor_sync(0xffffffffu, lsa, 2);
    lsb += __shfl_xor_sync(0xffffffffu, lsb, 1);
    lsb += __shfl_xor_sync(0xffffffffu, lsb, 2);
    if ((l & 3) == 0) {
        atomicAdd(&lsum[qal], lsa);
        atomicAdd(&lsum[qbl], lsb);
    }

    // ---- combine wk halves via Obuf (overlays Qh/Ql) and write out ----
    float* Obuf = (float*)smraw;  // 64 x 32 floats = 8KB
    if (wk == 1) {
        #pragma unroll
        for (int td = 0; td < 4; td++) {
            int n = 8 * td + 2 * (l & 3);
            *(float2*)&Obuf[qal * 32 + n] = make_float2(Oacc[td][0], Oacc[td][1]);
            *(float2*)&Obuf[qbl * 32 + n] = make_float2(Oacc[td][2], Oacc[td][3]);
        }
    }
    __syncthreads();
    if (wk == 0) {
        float rla = 1.0f / lsum[qal];
        float rlb = 1.0f / lsum[qbl];
        #pragma unroll
        for (int td = 0; td < 4; td++) {
            int n = 8 * td + 2 * (l & 3);
            float2 oa = *(const float2*)&Obuf[qal * 32 + n];
            float2 ob = *(const float2*)&Obuf[qbl * 32 + n];
            oa.x = (oa.x + Oacc[td][0]) * rla;
            oa.y = (oa.y + Oacc[td][1]) * rla;
            ob.x = (ob.x + Oacc[td][2]) * rlb;
            ob.y = (ob.y + Oacc[td][3]) * rlb;
            *(float2*)&out[((size_t)bb * 1024 + q0 + qal) * 256 + hh * 32 + n] = oa;
            *(float2*)&out[((size_t)bb * 1024 + q0 + qbl) * 256 + hh * 32 + n] = ob;
        }
    }
}

// ---------------------------------------------------------------------------
// Launch. Inputs: x, adj, mask, W_qkv, b_qkv, shifts, widths, self_loop_w
// ---------------------------------------------------------------------------
extern "C" void kernel_launch(void* const* d_in, const int* in_sizes, int n_in,
                              void* d_out, int out_size)
{
    const float*        x      = (const float*)d_in[0];
    const float*        adj    = (const float*)d_in[1];
    const unsigned int* mask   = (const unsigned int*)d_in[2];
    const float*        W_qkv  = (const float*)d_in[3];
    const float*        b_qkv  = (const float*)d_in[4];
    const float*        shifts = (const float*)d_in[5];
    const float*        widths = (const float*)d_in[6];
    const float*        slw    = (const float*)d_in[7];
    float*              out    = (float*)d_out;

    split_xw<<<(XN + WN) / 1024, 256>>>(x, W_qkv);
    qkv_gemm_mma<<<dim3(12, 128), 256>>>(b_qkv);
    moire_attn<<<dim3(8, 16, 8), 256>>>(adj, mask, shifts, widths, slw, out);
}

// round 8
// speedup vs baseline: 2.4346x; 1.0843x over previous
#include <cuda_runtime.h>
#include <cuda_bf16.h>
#include <cstdint>

#define B_ 8
#define N_ 1024
#define H_ 8
#define D_ 32
#define XN (8192 * 256)
#define WN (256 * 768)

// split-bf16 QKV scratch: [s][b][h][n][d], Q pre-scaled by 1/sqrt(D)
#define QKV_ELEMS (3u * B_ * H_ * N_ * D_)
__device__ __nv_bfloat16 g_hi[QKV_ELEMS];
__device__ __nv_bfloat16 g_lo[QKV_ELEMS];
// split-bf16 GEMM operands
__device__ __nv_bfloat16 g_xh[XN], g_xl[XN];
__device__ __nv_bfloat16 g_wh[WN], g_wl[WN];

// ---------------------------------------------------------------------------
// PTX helpers
// ---------------------------------------------------------------------------
__device__ __forceinline__ uint32_t sptr(const void* p) {
    return (uint32_t)__cvta_generic_to_shared(p);
}
__device__ __forceinline__ void ldmx4(uint32_t* r, uint32_t a) {
    asm volatile("ldmatrix.sync.aligned.m8n8.x4.shared.b16 {%0,%1,%2,%3}, [%4];"
                 : "=r"(r[0]), "=r"(r[1]), "=r"(r[2]), "=r"(r[3]) : "r"(a));
}
__device__ __forceinline__ void ldmx4t(uint32_t* r, uint32_t a) {
    asm volatile("ldmatrix.sync.aligned.m8n8.x4.trans.shared.b16 {%0,%1,%2,%3}, [%4];"
                 : "=r"(r[0]), "=r"(r[1]), "=r"(r[2]), "=r"(r[3]) : "r"(a));
}
__device__ __forceinline__ void ldmx2t(uint32_t* r, uint32_t a) {
    asm volatile("ldmatrix.sync.aligned.m8n8.x2.trans.shared.b16 {%0,%1}, [%2];"
                 : "=r"(r[0]), "=r"(r[1]) : "r"(a));
}
__device__ __forceinline__ void mma_bf16(float* d, const uint32_t* a,
                                         uint32_t b0, uint32_t b1) {
    asm volatile("mma.sync.aligned.m16n8k16.row.col.f32.bf16.bf16.f32 "
                 "{%0,%1,%2,%3}, {%4,%5,%6,%7}, {%8,%9}, {%0,%1,%2,%3};"
                 : "+f"(d[0]), "+f"(d[1]), "+f"(d[2]), "+f"(d[3])
                 : "r"(a[0]), "r"(a[1]), "r"(a[2]), "r"(a[3]), "r"(b0), "r"(b1));
}
// pack two fp32 -> bf16x2 (first arg -> low half) — convention proven in R5
__device__ __forceinline__ uint32_t packbf(float lo, float hi) {
    uint32_t r;
    asm("cvt.rn.bf16x2.f32 %0, %1, %2;" : "=r"(r) : "f"(hi), "f"(lo));
    return r;
}
__device__ __forceinline__ float2 bf2f(uint32_t u) {
    __nv_bfloat162 t = *reinterpret_cast<__nv_bfloat162*>(&u);
    return __bfloat1622float2(t);
}
__device__ __forceinline__ void cpa16(uint32_t dst, const void* src) {
    asm volatile("cp.async.cg.shared.global [%0], [%1], 16;" :: "r"(dst), "l"(src));
}
#define CP_COMMIT asm volatile("cp.async.commit_group;")
#define CP_WAIT0  asm volatile("cp.async.wait_group 0;")
#define CP_WAIT1  asm volatile("cp.async.wait_group 1;")

// ---------------------------------------------------------------------------
// Kernel 0: split x and W into bf16 hi/lo.
// ---------------------------------------------------------------------------
__global__ __launch_bounds__(256) void split_xw(
    const float* __restrict__ x, const float* __restrict__ W)
{
    int i4 = (blockIdx.x * 256 + threadIdx.x) * 4;
    const float* src;
    __nv_bfloat16 *dh, *dl;
    int off;
    if (i4 < XN) {
        src = x; dh = g_xh; dl = g_xl; off = i4;
    } else {
        off = i4 - XN;
        if (off >= WN) return;
        src = W; dh = g_wh; dl = g_wl;
    }
    float4 v = *(const float4*)(src + off);
    uint32_t h01 = packbf(v.x, v.y), h23 = packbf(v.z, v.w);
    float2 f01 = bf2f(h01), f23 = bf2f(h23);
    *(uint2*)&dh[off] = make_uint2(h01, h23);
    *(uint2*)&dl[off] = make_uint2(packbf(v.x - f01.x, v.y - f01.y),
                                   packbf(v.z - f23.x, v.w - f23.y));
}

// ---------------------------------------------------------------------------
// Kernel 1: QKV projection via split-bf16 MMA, 3-stage cp.async pipeline,
// ONE sync per K-chunk. Dynamic smem = 3 * 19456 bytes.
// ---------------------------------------------------------------------------
__global__ __launch_bounds__(256) void qkv_gemm_mma(const float* __restrict__ bias)
{
    extern __shared__ __align__(16) unsigned char smg[];
    const int tid = threadIdx.x;
    const int w = tid >> 5, l = tid & 31;
    const int l16 = l & 15;
    const int mw = 32 * (w & 1);
    const int nw = 16 * (w >> 1);
    const int rb = blockIdx.y * 64;
    const int cb = blockIdx.x * 64;

    const int xrow = tid >> 2, xpart = tid & 3;
    const int wrow = tid >> 3, wpart = tid & 7;

    auto stage = [&](int k0, unsigned char* buf) {
        cpa16(sptr(buf + xrow * 80 + xpart * 16),
              g_xh + (size_t)(rb + xrow) * 256 + k0 + xpart * 8);
        cpa16(sptr(buf + 5120 + xrow * 80 + xpart * 16),
              g_xl + (size_t)(rb + xrow) * 256 + k0 + xpart * 8);
        cpa16(sptr(buf + 10240 + wrow * 144 + wpart * 16),
              g_wh + (size_t)(k0 + wrow) * 768 + cb + wpart * 8);
        cpa16(sptr(buf + 14848 + wrow * 144 + wpart * 16),
              g_wl + (size_t)(k0 + wrow) * 768 + cb + wpart * 8);
    };

    float acc[2][2][4] = {};

    stage(0, smg);            CP_COMMIT;
    stage(32, smg + 19456);   CP_COMMIT;

    for (int c = 0; c < 8; c++) {
        if (c < 7) { CP_WAIT1; } else { CP_WAIT0; }
        __syncthreads();
        if (c < 6) {
            stage((c + 2) * 32, smg + ((c + 2) % 3) * 19456);
            CP_COMMIT;
        }
        unsigned char* buf = smg + (c % 3) * 19456;
        const __nv_bfloat16* xh = (const __nv_bfloat16*)(buf);
        const __nv_bfloat16* xl = (const __nv_bfloat16*)(buf + 5120);
        const __nv_bfloat16* wh = (const __nv_bfloat16*)(buf + 10240);
        const __nv_bfloat16* wl = (const __nv_bfloat16*)(buf + 14848);

        #pragma unroll
        for (int ks = 0; ks < 2; ks++) {
            uint32_t ah[2][4], al[2][4];
            #pragma unroll
            for (int mf = 0; mf < 2; mf++) {
                int aoff = (mw + 16 * mf + l16) * 40 + ks * 16 + ((l & 16) >> 1);
                ldmx4(ah[mf], sptr(xh + aoff));
                ldmx4(al[mf], sptr(xl + aoff));
            }
            #pragma unroll
            for (int t = 0; t < 2; t++) {
                int woff = (ks * 16 + l16) * 72 + nw + 8 * t;
                uint32_t bh[2], bl[2];
                ldmx2t(bh, sptr(wh + woff));
                ldmx2t(bl, sptr(wl + woff));
                #pragma unroll
                for (int mf = 0; mf < 2; mf++) {
                    mma_bf16(acc[mf][t], ah[mf], bh[0], bh[1]);
                    mma_bf16(acc[mf][t], al[mf], bh[0], bh[1]);
                    mma_bf16(acc[mf][t], ah[mf], bl[0], bl[1]);
                }
            }
        }
    }

    #pragma unroll
    for (int t = 0; t < 2; t++) {
        int c0 = cb + nw + 8 * t + 2 * (l & 3);
        int s = c0 >> 8, rem = c0 & 255, h = rem >> 5, d = rem & 31;
        float sc = (s == 0) ? 0.17677669529663687f : 1.0f;
        float b0 = bias[c0], b1 = bias[c0 + 1];
        #pragma unroll
        for (int mf = 0; mf < 2; mf++) {
            #pragma unroll
            for (int rr = 0; rr < 2; rr++) {
                int r = rb + mw + 16 * mf + (l >> 2) + 8 * rr;
                int bq = r >> 10, n = r & 1023;
                float v0 = (acc[mf][t][2 * rr + 0] + b0) * sc;
                float v1 = (acc[mf][t][2 * rr + 1] + b1) * sc;
                uint32_t hv = packbf(v0, v1);
                float2 f = bf2f(hv);
                uint32_t lv = packbf(v0 - f.x, v1 - f.y);
                size_t idx = ((size_t)((s * 8 + bq) * 8 + h) * 1024 + n) * 32 + d;
                *(uint32_t*)&g_hi[idx] = hv;
                *(uint32_t*)&g_lo[idx] = lv;
            }
        }
    }
}

// ---------------------------------------------------------------------------
// Kernel 2: tensor-core moire attention, 3-stage cp.async K/V pipeline,
// ONE sync per iteration. V fragments via ldmatrix.x4.trans (2 tiles/load).
// Dynamic smem = 8192 + 3 * 20480 = 69632 bytes.
// ---------------------------------------------------------------------------
__global__ __launch_bounds__(256, 2) void moire_attn(
    const float* __restrict__ adj, const unsigned int* __restrict__ mask,
    const float* __restrict__ shifts, const float* __restrict__ widths,
    const float* __restrict__ slw, float* __restrict__ out)
{
    extern __shared__ __align__(16) unsigned char smraw[];

    const int hh = blockIdx.x;
    const int q0 = blockIdx.y * 64;
    const int bb = blockIdx.z;
    const int tid = threadIdx.x;
    const int w   = tid >> 5;
    const int l   = tid & 31;
    const int wm  = w & 3;
    const int wk  = w >> 2;
    const int m0  = 16 * wm;
    const int n0k = 32 * wk;
    const int l16 = l & 15;
    const int qal = m0 + (l >> 2);
    const int qbl = qal + 8;

    const float sh   = shifts[hh];
    const float invw = 1.0f / fmaxf(widths[hh], 0.5f);
    const float sl   = slw[hh];
    const float LOGEPS = -13.815510557964274f;

    const size_t qbase = ((size_t)((0 * 8 + bb) * 8 + hh)) * 1024 * 32;
    const size_t kbase = ((size_t)((1 * 8 + bb) * 8 + hh)) * 1024 * 32;
    const size_t vbase = ((size_t)((2 * 8 + bb) * 8 + hh)) * 1024 * 32;

    __nv_bfloat16* Qh = (__nv_bfloat16*)(smraw);
    __nv_bfloat16* Ql = (__nv_bfloat16*)(smraw + 4096);

    const int row = tid >> 2, part = tid & 3;

    auto stageKV = [&](int kb, unsigned char* buf) {
        size_t gk = kbase + (size_t)(kb + row) * 32 + part * 8;
        size_t gv = vbase + (size_t)(kb + row) * 32 + part * 8;
        cpa16(sptr(buf + row * 80 + part * 16),         g_hi + gk);
        cpa16(sptr(buf + 5120 + row * 80 + part * 16),  g_lo + gk);
        cpa16(sptr(buf + 10240 + row * 80 + part * 16), g_hi + gv);
        cpa16(sptr(buf + 15360 + row * 80 + part * 16), g_lo + gv);
    };

    // stage Q (plain LDG) + prefetch stages 0,1 of K/V
    {
        size_t gq = qbase + (size_t)(q0 + row) * 32 + part * 8;
        *(uint4*)(Qh + row * 32 + part * 8) = *(const uint4*)(g_hi + gq);
        *(uint4*)(Ql + row * 32 + part * 8) = *(const uint4*)(g_lo + gq);
    }
    stageKV(0, smraw + 8192);            CP_COMMIT;
    stageKV(64, smraw + 8192 + 20480);   CP_COMMIT;

    const bool mqa = (mask[(size_t)bb * 1024 + q0 + qal] != 0u);
    const bool mqb = (mask[(size_t)bb * 1024 + q0 + qbl] != 0u);
    __syncthreads();

    uint32_t qfh[2][4], qfl[2][4];
    #pragma unroll
    for (int ks = 0; ks < 2; ks++) {
        int off = (m0 + l16) * 32 + ks * 16 + ((l & 16) >> 1);
        ldmx4(qfh[ks], sptr(Qh + off));
        ldmx4(qfl[ks], sptr(Ql + off));
    }

    // V ldmatrix.x4.trans lane address components
    const int vmi = l >> 3, vr = l & 7;
    const int vrow_off = (vmi & 1) * 8 + vr;     // k within 16
    const int vcol_off = 8 * (vmi >> 1);         // second n8 tile select

    float Oacc[4][4] = {};
    float lsa = 0.0f, lsb = 0.0f;

    for (int it = 0; it < 16; it++) {
        const int kb = it * 64;
        // adj + mask prefetch (regs; overlaps pipeline drain)
        float2 av[2][4];
        uint2  mkp[4];
        {
            const float* ap = adj + ((size_t)(bb * 1024 + q0 + qal)) * 1024
                              + kb + n0k + 2 * (l & 3);
            const unsigned int* mp = mask + (size_t)bb * 1024 + kb + n0k + 2 * (l & 3);
            #pragma unroll
            for (int t = 0; t < 4; t++) {
                av[0][t] = *(const float2*)(ap + 8 * t);
                av[1][t] = *(const float2*)(ap + 8 * 1024 + 8 * t);
                mkp[t]   = *(const uint2*)(mp + 8 * t);
            }
        }
        if (it < 15) { CP_WAIT1; } else { CP_WAIT0; }
        __syncthreads();   // stage `it` visible to all; iter it-1 reads done
        if (it < 14) {
            // writes buffer (it+2)%3, last read in iter it-1 -> safe after sync
            stageKV(kb + 128, smraw + 8192 + ((it + 2) % 3) * 20480);
            CP_COMMIT;
        }

        unsigned char* buf = smraw + 8192 + (it % 3) * 20480;
        const __nv_bfloat16* Kh = (const __nv_bfloat16*)(buf);
        const __nv_bfloat16* Kl = (const __nv_bfloat16*)(buf + 5120);
        const __nv_bfloat16* Vh = (const __nv_bfloat16*)(buf + 10240);
        const __nv_bfloat16* Vl = (const __nv_bfloat16*)(buf + 15360);

        // ---- QK: 4 n8-tile accumulators; K B-frags via ldmatrix.x4 ----
        float acc[4][4] = {};
        #pragma unroll
        for (int ks = 0; ks < 2; ks++) {
            #pragma unroll
            for (int t2 = 0; t2 < 2; t2++) {
                int koff = (n0k + 16 * t2 + l16) * 40 + ks * 16 + ((l & 16) >> 1);
                uint32_t rh[4], rl[4];
                ldmx4(rh, sptr(Kh + koff));
                ldmx4(rl, sptr(Kl + koff));
                mma_bf16(acc[2 * t2],     qfh[ks], rh[0], rh[2]);
                mma_bf16(acc[2 * t2],     qfl[ks], rh[0], rh[2]);
                mma_bf16(acc[2 * t2],     qfh[ks], rl[0], rl[2]);
                mma_bf16(acc[2 * t2 + 1], qfh[ks], rh[1], rh[3]);
                mma_bf16(acc[2 * t2 + 1], qfl[ks], rh[1], rh[3]);
                mma_bf16(acc[2 * t2 + 1], qfh[ks], rl[1], rl[3]);
            }
        }

        // ---- elementwise: moire + self-loop + mask + exp(val-12) ----
        const bool diag = (kb == q0);
        #pragma unroll
        for (int t = 0; t < 4; t++) {
            int c0 = n0k + 8 * t + 2 * (l & 3);
            bool mk0 = (mkp[t].x != 0u), mk1 = (mkp[t].y != 0u);
            float ax = av[0][t].x - sh, ay = av[0][t].y - sh;
            float bx = av[1][t].x - sh, by = av[1][t].y - sh;
            float v00 = acc[t][0] + fmaxf(-ax * ax * invw, LOGEPS);
            float v01 = acc[t][1] + fmaxf(-ay * ay * invw, LOGEPS);
            float v10 = acc[t][2] + fmaxf(-bx * bx * invw, LOGEPS);
            float v11 = acc[t][3] + fmaxf(-by * by * invw, LOGEPS);
            if (diag) {
                if (qal == c0)     v00 += sl;
                if (qal == c0 + 1) v01 += sl;
                if (qbl == c0)     v10 += sl;
                if (qbl == c0 + 1) v11 += sl;
            }
            float w00 = mqa ? (mk0 ? __expf(v00 - 12.0f) : 0.0f) : 1.0f;
            float w01 = mqa ? (mk1 ? __expf(v01 - 12.0f) : 0.0f) : 1.0f;
            float w10 = mqb ? (mk0 ? __expf(v10 - 12.0f) : 0.0f) : 1.0f;
            float w11 = mqb ? (mk1 ? __expf(v11 - 12.0f) : 0.0f) : 1.0f;
            lsa += w00 + w01;
            lsb += w10 + w11;
            acc[t][0] = w00; acc[t][1] = w01; acc[t][2] = w10; acc[t][3] = w11;
        }

        // ---- P fragments (accumulator layout == A-fragment layout) ----
        uint32_t pfh[2][4], pfl[2][4];
        #pragma unroll
        for (int cch = 0; cch < 2; cch++) {
            #pragma unroll
            for (int rr = 0; rr < 2; rr++) {
                const float* a4 = acc[2 * cch + rr];
                uint32_t u0 = packbf(a4[0], a4[1]);
                uint32_t u1 = packbf(a4[2], a4[3]);
                float2 f0 = bf2f(u0), f1 = bf2f(u1);
                pfh[cch][rr * 2 + 0] = u0;
                pfh[cch][rr * 2 + 1] = u1;
                pfl[cch][rr * 2 + 0] = packbf(a4[0] - f0.x, a4[1] - f0.y);
                pfl[cch][rr * 2 + 1] = packbf(a4[2] - f1.x, a4[3] - f1.y);
            }
        }

        // ---- PV: O += Ph@Vh + Pl@Vh + Ph@Vl; V frags via x4.trans ----
        #pragma unroll
        for (int cch = 0; cch < 2; cch++) {
            #pragma unroll
            for (int tdp = 0; tdp < 2; tdp++) {
                int voff = (n0k + 16 * cch + vrow_off) * 40 + 8 * (2 * tdp) + vcol_off;
                uint32_t rvh[4], rvl[4];
                ldmx4t(rvh, sptr(Vh + voff));
                ldmx4t(rvl, sptr(Vl + voff));
                mma_bf16(Oacc[2 * tdp],     pfh[cch], rvh[0], rvh[1]);
                mma_bf16(Oacc[2 * tdp],     pfl[cch], rvh[0], rvh[1]);
                mma_bf16(Oacc[2 * tdp],     pfh[cch], rvl[0], rvl[1]);
                mma_bf16(Oacc[2 * tdp + 1], pfh[cch], rvh[2], rvh[3]);
                mma_bf16(Oacc[2 * tdp + 1], pfl[cch], rvh[2], rvh[3]);
                mma_bf16(Oacc[2 * tdp + 1], pfh[cch], rvl[2], rvl[3]);
            }
        }
    }

    // ---- lsum: zero (overlay on stage area), reduce, accumulate ----
    __syncthreads();
    float* lsum = (float*)(smraw + 8192);
    if (tid < 64) lsum[tid] = 0.0f;
    __syncthreads();
    lsa += __shfl_xor_sync(0xffffffffu, lsa, 1);
    lsa += __shfl_xor_sync(0xffffffffu, lsa, 2);
    lsb += __shfl_xor_sync(0xffffffffu, lsb, 1);
    lsb += __shfl_xor_sync(0xffffffffu, lsb, 2);
    if ((l & 3) == 0) {
        atomicAdd(&lsum[qal], lsa);
        atomicAdd(&lsum[qbl], lsb);
    }

    // ---- combine wk halves via Obuf (overlays Qh/Ql) and write out ----
    float* Obuf = (float*)smraw;  // 64 x 32 floats = 8KB
    if (wk == 1) {
        #pragma unroll
        for (int td = 0; td < 4; td++) {
            int n = 8 * td + 2 * (l & 3);
            *(float2*)&Obuf[qal * 32 + n] = make_float2(Oacc[td][0], Oacc[td][1]);
            *(float2*)&Obuf[qbl * 32 + n] = make_float2(Oacc[td][2], Oacc[td][3]);
        }
    }
    __syncthreads();
    if (wk == 0) {
        float rla = 1.0f / lsum[qal];
        float rlb = 1.0f / lsum[qbl];
        #pragma unroll
        for (int td = 0; td < 4; td++) {
            int n = 8 * td + 2 * (l & 3);
            float2 oa = *(const float2*)&Obuf[qal * 32 + n];
            float2 ob = *(const float2*)&Obuf[qbl * 32 + n];
            oa.x = (oa.x + Oacc[td][0]) * rla;
            oa.y = (oa.y + Oacc[td][1]) * rla;
            ob.x = (ob.x + Oacc[td][2]) * rlb;
            ob.y = (ob.y + Oacc[td][3]) * rlb;
            *(float2*)&out[((size_t)bb * 1024 + q0 + qal) * 256 + hh * 32 + n] = oa;
            *(float2*)&out[((size_t)bb * 1024 + q0 + qbl) * 256 + hh * 32 + n] = ob;
        }
    }
}

// ---------------------------------------------------------------------------
// Launch. Inputs: x, adj, mask, W_qkv, b_qkv, shifts, widths, self_loop_w
// ---------------------------------------------------------------------------
extern "C" void kernel_launch(void* const* d_in, const int* in_sizes, int n_in,
                              void* d_out, int out_size)
{
    const float*        x      = (const float*)d_in[0];
    const float*        adj    = (const float*)d_in[1];
    const unsigned int* mask   = (const unsigned int*)d_in[2];
    const float*        W_qkv  = (const float*)d_in[3];
    const float*        b_qkv  = (const float*)d_in[4];
    const float*        shifts = (const float*)d_in[5];
    const float*        widths = (const float*)d_in[6];
    const float*        slw    = (const float*)d_in[7];
    float*              out    = (float*)d_out;

    static bool attr_done = false;
    if (!attr_done) {
        cudaFuncSetAttribute(qkv_gemm_mma,
            cudaFuncAttributeMaxDynamicSharedMemorySize, 3 * 19456);
        cudaFuncSetAttribute(moire_attn,
            cudaFuncAttributeMaxDynamicSharedMemorySize, 8192 + 3 * 20480);
        attr_done = true;
    }

    split_xw<<<(XN + WN) / 1024, 256>>>(x, W_qkv);
    qkv_gemm_mma<<<dim3(12, 128), 256, 3 * 19456>>>(b_qkv);
    moire_attn<<<dim3(8, 16, 8), 256, 8192 + 3 * 20480>>>(
        adj, mask, shifts, widths, slw, out);
}